// round 2
// baseline (speedup 1.0000x reference)
#include <cuda_runtime.h>
#include <cuda_bf16.h>
#include <cstdint>
#include <cstddef>

#define HD   1024
#define NHEADS 16
#define DHEAD  64
#define TT     64
#define TSZ   256
#define NBITS   8
#define KSEL    8
#define NTOK 4096
#define SEQ  2048
#define NB      2

// ---------------- scratch (static device globals; no allocs allowed) ----------
__device__ float g_x   [NTOK * HD];
__device__ float g_q   [NTOK * HD];
__device__ float g_k   [NTOK * HD];
__device__ float g_v   [NTOK * HD];
__device__ float g_ctx [NTOK * HD];
__device__ float g_attn[NTOK * HD];
__device__ float g_y   [NTOK * HD];
__device__ float g_hs  [NTOK * TT * NBITS];
__device__ float g_w   [NTOK * TT * KSEL];
__device__ int   g_i   [NTOK * TT * KSEL];

// ---------------- LayerNorm: one block per row of 1024 ------------------------
__global__ void __launch_bounds__(256) ln_kernel(const float* __restrict__ in,
                                                 const float* __restrict__ gamma,
                                                 const float* __restrict__ beta,
                                                 float* __restrict__ out)
{
    const int row = blockIdx.x;
    const int tid = threadIdx.x;
    const float4 v = *(const float4*)(in + (size_t)row * HD + tid * 4);
    float s  = v.x + v.y + v.z + v.w;
    float sq = v.x * v.x + v.y * v.y + v.z * v.z + v.w * v.w;

    __shared__ float rs[8], rq[8];
    __shared__ float smean, sinv;
    const int lane = tid & 31, wid = tid >> 5;
#pragma unroll
    for (int off = 16; off; off >>= 1) {
        s  += __shfl_down_sync(0xffffffffu, s,  off);
        sq += __shfl_down_sync(0xffffffffu, sq, off);
    }
    if (lane == 0) { rs[wid] = s; rq[wid] = sq; }
    __syncthreads();
    if (tid == 0) {
        float ts = 0.f, tq = 0.f;
#pragma unroll
        for (int i = 0; i < 8; i++) { ts += rs[i]; tq += rq[i]; }
        const float mean = ts * (1.f / HD);
        const float var  = tq * (1.f / HD) - mean * mean;
        smean = mean;
        sinv  = rsqrtf(var + 1e-12f);
    }
    __syncthreads();
    const float mean = smean, inv = sinv;
    const float4 gv = *(const float4*)(gamma + tid * 4);
    const float4 bv = *(const float4*)(beta  + tid * 4);
    float4 o;
    o.x = (v.x - mean) * inv * gv.x + bv.x;
    o.y = (v.y - mean) * inv * gv.y + bv.y;
    o.z = (v.z - mean) * inv * gv.z + bv.z;
    o.w = (v.w - mean) * inv * gv.w + bv.w;
    *(float4*)(out + (size_t)row * HD + tid * 4) = o;
}

// ---------------- SGEMM 128x128x8, 256 threads, 8x8/thread --------------------
// C[r, c] = sum_k A[r,k]*B[k,c] + bias[c] (+ res[r,c] if res != nullptr)
__global__ void __launch_bounds__(256) gemm_kernel(const float* __restrict__ A,
                                                   const float* __restrict__ B,
                                                   const float* __restrict__ bias,
                                                   const float* __restrict__ res,
                                                   float* __restrict__ C,
                                                   int Kd, int ldb, int ldc)
{
    __shared__ float As[8][128];
    __shared__ float Bs[8][128];
    const int tid = threadIdx.x;
    const int bm = blockIdx.y, bn = blockIdx.x;
    const int arow = tid >> 1, acol = (tid & 1) * 4;
    const int brow = tid >> 5, bcol = (tid & 31) * 4;
    const float* Ap = A + (size_t)(bm * 128 + arow) * Kd + acol;
    const float* Bp = B + (size_t)brow * ldb + bn * 128 + bcol;
    const int tx = tid & 15, ty = tid >> 4;

    float acc[8][8];
#pragma unroll
    for (int i = 0; i < 8; i++)
#pragma unroll
        for (int j = 0; j < 8; j++) acc[i][j] = 0.f;

    for (int k0 = 0; k0 < Kd; k0 += 8) {
        const float4 av = *(const float4*)Ap;
        const float4 bv = *(const float4*)Bp;
        Ap += 8;
        Bp += (size_t)8 * ldb;
        As[acol + 0][arow] = av.x;
        As[acol + 1][arow] = av.y;
        As[acol + 2][arow] = av.z;
        As[acol + 3][arow] = av.w;
        *(float4*)&Bs[brow][bcol] = bv;
        __syncthreads();
#pragma unroll
        for (int kk = 0; kk < 8; kk++) {
            const float4 a0 = *(const float4*)&As[kk][ty * 4];
            const float4 a1 = *(const float4*)&As[kk][64 + ty * 4];
            const float4 b0 = *(const float4*)&Bs[kk][tx * 4];
            const float4 b1 = *(const float4*)&Bs[kk][64 + tx * 4];
            const float a[8] = {a0.x, a0.y, a0.z, a0.w, a1.x, a1.y, a1.z, a1.w};
            const float b[8] = {b0.x, b0.y, b0.z, b0.w, b1.x, b1.y, b1.z, b1.w};
#pragma unroll
            for (int i = 0; i < 8; i++)
#pragma unroll
                for (int j = 0; j < 8; j++) acc[i][j] += a[i] * b[j];
        }
        __syncthreads();
    }

#pragma unroll
    for (int i = 0; i < 8; i++) {
        const int r = bm * 128 + ((i < 4) ? (ty * 4 + i) : (64 + ty * 4 + (i - 4)));
#pragma unroll
        for (int jh = 0; jh < 2; jh++) {
            const int c = bn * 128 + ((jh == 0) ? (tx * 4) : (64 + tx * 4));
            float4 o;
            o.x = acc[i][jh * 4 + 0];
            o.y = acc[i][jh * 4 + 1];
            o.z = acc[i][jh * 4 + 2];
            o.w = acc[i][jh * 4 + 3];
            const float4 bb = *(const float4*)&bias[c];
            o.x += bb.x; o.y += bb.y; o.z += bb.z; o.w += bb.w;
            if (res) {
                const float4 rr = *(const float4*)&res[(size_t)r * ldc + c];
                o.x += rr.x; o.y += rr.y; o.z += rr.z; o.w += rr.w;
            }
            *(float4*)&C[(size_t)r * ldc + c] = o;
        }
    }
}

// ---------------- Flash attention fp32: 1 query row / thread ------------------
// grid (SEQ/64, NHEADS, NB), 64 threads. KV tiles of 32 rows in smem.
__global__ void __launch_bounds__(64) attn_kernel(const float* __restrict__ q,
                                                  const float* __restrict__ k,
                                                  const float* __restrict__ v,
                                                  const float* __restrict__ mask,
                                                  float* __restrict__ ctx)
{
    const int qt = blockIdx.x, head = blockIdx.y, b = blockIdx.z;
    const int t = threadIdx.x;
    __shared__ float Ks[32][64];
    __shared__ float Vs[32][64];
    __shared__ float Msk[32];

    const size_t qrow = (size_t)(b * SEQ + qt * 64 + t);
    const float4* qp = (const float4*)(q + qrow * HD + head * DHEAD);
    float4 qv[16];
#pragma unroll
    for (int i = 0; i < 16; i++) qv[i] = qp[i];
    float4 oa[16];
#pragma unroll
    for (int i = 0; i < 16; i++) oa[i] = make_float4(0.f, 0.f, 0.f, 0.f);
    float m = -1e30f, l = 0.f;

    for (int kt = 0; kt < SEQ / 32; kt++) {
        __syncthreads();
        {
            const int r = t >> 1, half = t & 1;
            const size_t krow = (size_t)(b * SEQ + kt * 32 + r);
            const float4* kp = (const float4*)(k + krow * HD + head * DHEAD) + half * 8;
            const float4* vp = (const float4*)(v + krow * HD + head * DHEAD) + half * 8;
            float4* kd = (float4*)&Ks[r][half * 32];
            float4* vd = (float4*)&Vs[r][half * 32];
#pragma unroll
            for (int i = 0; i < 8; i++) { kd[i] = kp[i]; vd[i] = vp[i]; }
            if (t < 32) Msk[t] = -1000.f * (1.f - mask[b * SEQ + kt * 32 + t]);
        }
        __syncthreads();

        float s[32];
#pragma unroll 4
        for (int j = 0; j < 32; j++) {
            const float4* kr = (const float4*)Ks[j];
            float acc = 0.f;
#pragma unroll
            for (int d = 0; d < 16; d++) {
                const float4 kv = kr[d];
                acc += qv[d].x * kv.x + qv[d].y * kv.y + qv[d].z * kv.z + qv[d].w * kv.w;
            }
            s[j] = acc * 0.125f + Msk[j];
        }
        float mt = m;
#pragma unroll
        for (int j = 0; j < 32; j++) mt = fmaxf(mt, s[j]);
        const float corr = __expf(m - mt);
        l *= corr;
#pragma unroll
        for (int i = 0; i < 16; i++) {
            oa[i].x *= corr; oa[i].y *= corr; oa[i].z *= corr; oa[i].w *= corr;
        }
#pragma unroll 4
        for (int j = 0; j < 32; j++) {
            const float p = __expf(s[j] - mt);
            l += p;
            const float4* vr = (const float4*)Vs[j];
#pragma unroll
            for (int d = 0; d < 16; d++) {
                const float4 vv = vr[d];
                oa[d].x += p * vv.x; oa[d].y += p * vv.y;
                oa[d].z += p * vv.z; oa[d].w += p * vv.w;
            }
        }
        m = mt;
    }

    const float inv = 1.f / l;
    float4* op = (float4*)(ctx + qrow * HD + head * DHEAD);
#pragma unroll
    for (int i = 0; i < 16; i++) {
        float4 o = oa[i];
        o.x *= inv; o.y *= inv; o.z *= inv; o.w *= inv;
        op[i] = o;
    }
}

// ---------------- top-k over 256 sign-pattern logits: 1 warp per (n,t) -------
__global__ void __launch_bounds__(256) topk_kernel(const float* __restrict__ hs,
                                                   float* __restrict__ wout,
                                                   int* __restrict__ iout)
{
    const int warp = (blockIdx.x * blockDim.x + threadIdx.x) >> 5;
    const int lane = threadIdx.x & 31;
    const float* hp = hs + (size_t)warp * 8;
    float h[8];
#pragma unroll
    for (int i = 0; i < 8; i++) h[i] = hp[i];

    float lg[8];
#pragma unroll
    for (int i = 0; i < 8; i++) {
        const int c = lane * 8 + i;
        float acc = 0.f;
#pragma unroll
        for (int bb = 0; bb < 8; bb++)
            acc += ((c >> bb) & 1) ? h[bb] : -h[bb];
        lg[i] = acc;
    }

    float m0 = 0.f, sum = 0.f, myv = 0.f;
    int myc = 0;
#pragma unroll
    for (int it = 0; it < 8; it++) {
        float lv = -1e30f;
        int lc = 0;
#pragma unroll
        for (int i = 0; i < 8; i++)
            if (lg[i] > lv) { lv = lg[i]; lc = lane * 8 + i; }
#pragma unroll
        for (int off = 16; off; off >>= 1) {
            const float ov = __shfl_down_sync(0xffffffffu, lv, off);
            const int   oc = __shfl_down_sync(0xffffffffu, lc, off);
            if (ov > lv || (ov == lv && oc < lc)) { lv = ov; lc = oc; }
        }
        lv = __shfl_sync(0xffffffffu, lv, 0);
        lc = __shfl_sync(0xffffffffu, lc, 0);
        if (it == 0) m0 = lv;
        sum += __expf(lv - m0);
        if (lane == it) { myv = lv; myc = lc; }
        if (lane == (lc >> 3)) {
            const int ii = lc & 7;
#pragma unroll
            for (int i = 0; i < 8; i++)
                if (i == ii) lg[i] = -1e30f;
        }
    }
    if (lane < 8) {
        wout[(size_t)warp * 8 + lane] = __expf(myv - m0) / sum;
        iout[(size_t)warp * 8 + lane] = myc;
    }
}

// ---------------- gather FFN + residual: 1 block per token --------------------
__global__ void __launch_bounds__(256) ffn_kernel(const float* __restrict__ tables,
                                                  const float* __restrict__ tbias,
                                                  const float* __restrict__ attn,
                                                  const float* __restrict__ wbuf,
                                                  const int* __restrict__ ibuf,
                                                  float* __restrict__ out)
{
    const int n = blockIdx.x;
    const int tid = threadIdx.x;
    __shared__ float sw[512];
    __shared__ int   si[512];
    sw[tid]       = wbuf[(size_t)n * 512 + tid];
    sw[tid + 256] = wbuf[(size_t)n * 512 + 256 + tid];
    si[tid]       = ibuf[(size_t)n * 512 + tid];
    si[tid + 256] = ibuf[(size_t)n * 512 + 256 + tid];
    __syncthreads();

    float4 acc = make_float4(0.f, 0.f, 0.f, 0.f);
    const int hb = tid * 4;
#pragma unroll 4
    for (int p = 0; p < 512; p++) {
        const int tt = p >> 3;
        const float4 row = *(const float4*)&tables[((size_t)tt * TSZ + si[p]) * HD + hb];
        const float wv = sw[p];
        acc.x += wv * row.x; acc.y += wv * row.y;
        acc.z += wv * row.z; acc.w += wv * row.w;
    }
    const float4 bb = *(const float4*)&tbias[hb];
    const float4 aa = *(const float4*)&attn[(size_t)n * HD + hb];
    float4 o;
    o.x = acc.x + bb.x + aa.x;
    o.y = acc.y + bb.y + aa.y;
    o.z = acc.z + bb.z + aa.z;
    o.w = acc.w + bb.w + aa.w;
    *(float4*)&out[(size_t)n * HD + hb] = o;
}

// ---------------- launcher ----------------------------------------------------
extern "C" void kernel_launch(void* const* d_in, const int* in_sizes, int n_in,
                              void* d_out, int out_size)
{
    const float* hidden = (const float*)d_in[0];
    const float* amask  = (const float*)d_in[1];
    const float* ln1g   = (const float*)d_in[2];
    const float* ln1b   = (const float*)d_in[3];
    const float* Wq     = (const float*)d_in[4];
    const float* bq     = (const float*)d_in[5];
    const float* Wk     = (const float*)d_in[6];
    const float* bk     = (const float*)d_in[7];
    const float* Wv     = (const float*)d_in[8];
    const float* bv     = (const float*)d_in[9];
    const float* Wo     = (const float*)d_in[10];
    const float* bo     = (const float*)d_in[11];
    const float* ln2g   = (const float*)d_in[12];
    const float* ln2b   = (const float*)d_in[13];
    const float* Wh     = (const float*)d_in[14];
    const float* bh     = (const float*)d_in[15];
    const float* tw     = (const float*)d_in[16];
    const float* tb     = (const float*)d_in[17];
    float* out = (float*)d_out;

    float *x, *q, *k, *v, *ctx, *attn, *y, *hsb, *wb;
    int* ib;
    cudaGetSymbolAddress((void**)&x,    g_x);
    cudaGetSymbolAddress((void**)&q,    g_q);
    cudaGetSymbolAddress((void**)&k,    g_k);
    cudaGetSymbolAddress((void**)&v,    g_v);
    cudaGetSymbolAddress((void**)&ctx,  g_ctx);
    cudaGetSymbolAddress((void**)&attn, g_attn);
    cudaGetSymbolAddress((void**)&y,    g_y);
    cudaGetSymbolAddress((void**)&hsb,  g_hs);
    cudaGetSymbolAddress((void**)&wb,   g_w);
    cudaGetSymbolAddress((void**)&ib,   g_i);

    // 1. LN1
    ln_kernel<<<NTOK, 256>>>(hidden, ln1g, ln1b, x);

    // 2. QKV projections
    dim3 gqkv(HD / 128, NTOK / 128);
    gemm_kernel<<<gqkv, 256>>>(x, Wq, bq, nullptr, q, HD, HD, HD);
    gemm_kernel<<<gqkv, 256>>>(x, Wk, bk, nullptr, k, HD, HD, HD);
    gemm_kernel<<<gqkv, 256>>>(x, Wv, bv, nullptr, v, HD, HD, HD);

    // 3. attention
    attn_kernel<<<dim3(SEQ / 64, NHEADS, NB), 64>>>(q, k, v, amask, ctx);

    // 4. output projection + residual
    gemm_kernel<<<gqkv, 256>>>(ctx, Wo, bo, hidden, attn, HD, HD, HD);

    // 5. LN2
    ln_kernel<<<NTOK, 256>>>(attn, ln2g, ln2b, y);

    // 6. table-head projection (first 512 cols of Wh)
    gemm_kernel<<<dim3(512 / 128, NTOK / 128), 256>>>(y, Wh, bh, nullptr, hsb, HD, HD, 512);

    // 7. sign-pattern logits + top-8 + softmax weights
    topk_kernel<<<(NTOK * TT) / 8, 256>>>(hsb, wb, ib);

    // 8. gather FFN + bias + attn residual -> out
    ffn_kernel<<<NTOK, 256>>>(tw, tb, attn, wb, ib, out);
}

// round 5
// speedup vs baseline: 1.0161x; 1.0161x over previous
#include <cuda_runtime.h>
#include <cuda_bf16.h>
#include <cstdint>
#include <cstddef>

#define HD   1024
#define NHEADS 16
#define DHEAD  64
#define TT     64
#define TSZ   256
#define NBITS   8
#define KSEL    8
#define NTOK 4096
#define SEQ  2048
#define NB      2

typedef unsigned long long u64;

// ---------------- scratch (static device globals; no allocs allowed) ----------
__device__ float g_x   [NTOK * HD];
__device__ float g_q   [NTOK * HD];
__device__ float g_k   [NTOK * HD];
__device__ float g_v   [NTOK * HD];
__device__ float g_ctx [NTOK * HD];
__device__ float g_attn[NTOK * HD];
__device__ float g_y   [NTOK * HD];
__device__ float g_hs  [NTOK * TT * NBITS];
__device__ float g_w   [NTOK * TT * KSEL];
__device__ int   g_i   [NTOK * TT * KSEL];
__device__ __nv_bfloat16 g_tbl[TT * TSZ * HD];

// ---------------- small helpers ----------------------------------------------
__device__ __forceinline__ float tf32r(float x) {
    uint32_t r;
    asm("cvt.rna.tf32.f32 %0, %1;" : "=r"(r) : "f"(x));
    return __uint_as_float(r);
}
__device__ __forceinline__ void split_tf32(float x, uint32_t& hi, uint32_t& lo) {
    const float h = tf32r(x);
    hi = __float_as_uint(h);
    lo = __float_as_uint(tf32r(x - h));
}
__device__ __forceinline__ u64 fma2(u64 a, u64 b, u64 c) {
    u64 d;
    asm("fma.rn.f32x2 %0, %1, %2, %3;" : "=l"(d) : "l"(a), "l"(b), "l"(c));
    return d;
}
__device__ __forceinline__ u64 mul2(u64 a, u64 b) {
    u64 d;
    asm("mul.rn.f32x2 %0, %1, %2;" : "=l"(d) : "l"(a), "l"(b));
    return d;
}
__device__ __forceinline__ u64 pk2(float x, float y) {
    u64 r;
    asm("mov.b64 %0, {%1, %2};" : "=l"(r) : "f"(x), "f"(y));
    return r;
}
__device__ __forceinline__ float2 unpk2(u64 v) {
    float2 r;
    asm("mov.b64 {%0, %1}, %2;" : "=f"(r.x), "=f"(r.y) : "l"(v));
    return r;
}
__device__ __forceinline__ void mma_tf32(float* acc, const uint32_t* a, const uint32_t* b) {
    asm volatile(
        "mma.sync.aligned.m16n8k8.row.col.f32.tf32.tf32.f32 "
        "{%0,%1,%2,%3}, {%4,%5,%6,%7}, {%8,%9}, {%0,%1,%2,%3};\n"
        : "+f"(acc[0]), "+f"(acc[1]), "+f"(acc[2]), "+f"(acc[3])
        : "r"(a[0]), "r"(a[1]), "r"(a[2]), "r"(a[3]), "r"(b[0]), "r"(b[1]));
}

// ---------------- fp32 -> bf16 table conversion -------------------------------
__global__ void __launch_bounds__(256) tbl_bf16_kernel(const float* __restrict__ in,
                                                       __nv_bfloat16* __restrict__ out)
{
    const size_t i = ((size_t)blockIdx.x * 256 + threadIdx.x) * 8;
    const float4 a = *(const float4*)(in + i);
    const float4 b = *(const float4*)(in + i + 4);
    __nv_bfloat162 p0 = __float22bfloat162_rn(make_float2(a.x, a.y));
    __nv_bfloat162 p1 = __float22bfloat162_rn(make_float2(a.z, a.w));
    __nv_bfloat162 p2 = __float22bfloat162_rn(make_float2(b.x, b.y));
    __nv_bfloat162 p3 = __float22bfloat162_rn(make_float2(b.z, b.w));
    uint4 o;
    o.x = *(uint32_t*)&p0; o.y = *(uint32_t*)&p1;
    o.z = *(uint32_t*)&p2; o.w = *(uint32_t*)&p3;
    *(uint4*)(out + i) = o;
}

// ---------------- LayerNorm: one block per row of 1024 ------------------------
__global__ void __launch_bounds__(256) ln_kernel(const float* __restrict__ in,
                                                 const float* __restrict__ gamma,
                                                 const float* __restrict__ beta,
                                                 float* __restrict__ out)
{
    const int row = blockIdx.x;
    const int tid = threadIdx.x;
    const float4 v = *(const float4*)(in + (size_t)row * HD + tid * 4);
    float s  = v.x + v.y + v.z + v.w;
    float sq = v.x * v.x + v.y * v.y + v.z * v.z + v.w * v.w;

    __shared__ float rs[8], rq[8];
    __shared__ float smean, sinv;
    const int lane = tid & 31, wid = tid >> 5;
#pragma unroll
    for (int off = 16; off; off >>= 1) {
        s  += __shfl_down_sync(0xffffffffu, s,  off);
        sq += __shfl_down_sync(0xffffffffu, sq, off);
    }
    if (lane == 0) { rs[wid] = s; rq[wid] = sq; }
    __syncthreads();
    if (tid == 0) {
        float ts = 0.f, tq = 0.f;
#pragma unroll
        for (int i = 0; i < 8; i++) { ts += rs[i]; tq += rq[i]; }
        const float mean = ts * (1.f / HD);
        const float var  = tq * (1.f / HD) - mean * mean;
        smean = mean;
        sinv  = rsqrtf(var + 1e-12f);
    }
    __syncthreads();
    const float mean = smean, inv = sinv;
    const float4 gv = *(const float4*)(gamma + tid * 4);
    const float4 bv = *(const float4*)(beta  + tid * 4);
    float4 o;
    o.x = (v.x - mean) * inv * gv.x + bv.x;
    o.y = (v.y - mean) * inv * gv.y + bv.y;
    o.z = (v.z - mean) * inv * gv.z + bv.z;
    o.w = (v.w - mean) * inv * gv.w + bv.w;
    *(float4*)(out + (size_t)row * HD + tid * 4) = o;
}

// ---------------- 3xTF32 tensor-core GEMM 128x128x32, 8 warps ----------------
// C[r,c] = sum_k A[r,k]*B[k,c] + bias[c] (+ res[r,c] if res)
// Full fp32 inputs; error-compensated tf32 (CUTLASS 3xTF32 scheme):
//   acc += A_lo*B_hi + A_hi*B_lo + A_hi*B_hi    (missing A_lo*B_lo ~ 2^-22)
__global__ void __launch_bounds__(256) gemm_tf32_kernel(const float* __restrict__ A,
                                                        const float* __restrict__ B,
                                                        const float* __restrict__ bias,
                                                        const float* __restrict__ res,
                                                        float* __restrict__ C,
                                                        int Kd, int ldb, int ldc)
{
    __shared__ float As[128][36];   // [m][k], pitch 36 -> conflict-free frag loads
    __shared__ float Bs[32][136];   // [k][n], pitch 136 -> conflict-free frag loads

    const int tid  = threadIdx.x;
    const int wrp  = tid >> 5;
    const int lane = tid & 31;
    const int g  = lane >> 2;      // groupID
    const int tg = lane & 3;       // threadID_in_group
    const int bm = blockIdx.y, bn = blockIdx.x;
    const int mwarp = (wrp >> 2) * 64;   // 2 warps along M
    const int nwarp = (wrp & 3) * 32;    // 4 warps along N

    // global load coords
    const int arow = tid >> 1, acol = (tid & 1) * 16;
    const int brow = tid >> 3, bcol = (tid & 7) * 16;
    const float* Ap = A + (size_t)(bm * 128 + arow) * Kd + acol;
    const float* Bp = B + (size_t)brow * ldb + bn * 128 + bcol;

    float acc[4][4][4];
#pragma unroll
    for (int mi = 0; mi < 4; mi++)
#pragma unroll
        for (int ni = 0; ni < 4; ni++)
#pragma unroll
            for (int c = 0; c < 4; c++) acc[mi][ni][c] = 0.f;

    for (int k0 = 0; k0 < Kd; k0 += 32) {
#pragma unroll
        for (int i = 0; i < 4; i++) {
            const float4 av = *(const float4*)(Ap + i * 4);
            *(float4*)&As[arow][acol + i * 4] = av;
            const float4 bv = *(const float4*)(Bp + i * 4);
            *(float4*)&Bs[brow][bcol + i * 4] = bv;
        }
        Ap += 32;
        Bp += (size_t)32 * ldb;
        __syncthreads();

#pragma unroll
        for (int ks = 0; ks < 4; ks++) {
            const int kk = ks * 8;
            uint32_t ah[4][4], al[4][4], bh[4][2], bl[4][2];
#pragma unroll
            for (int mi = 0; mi < 4; mi++) {
                const float* pa  = &As[mwarp + mi * 16 + g][kk + tg];
                const float* pa8 = pa + 8 * 36;
                split_tf32(pa[0],  ah[mi][0], al[mi][0]);
                split_tf32(pa8[0], ah[mi][1], al[mi][1]);
                split_tf32(pa[4],  ah[mi][2], al[mi][2]);
                split_tf32(pa8[4], ah[mi][3], al[mi][3]);
            }
#pragma unroll
            for (int ni = 0; ni < 4; ni++) {
                const float* pb = &Bs[kk + tg][nwarp + ni * 8 + g];
                split_tf32(pb[0],       bh[ni][0], bl[ni][0]);
                split_tf32(pb[4 * 136], bh[ni][1], bl[ni][1]);
            }
#pragma unroll
            for (int mi = 0; mi < 4; mi++)
#pragma unroll
                for (int ni = 0; ni < 4; ni++) {
                    mma_tf32(acc[mi][ni], al[mi], bh[ni]);
                    mma_tf32(acc[mi][ni], ah[mi], bl[ni]);
                    mma_tf32(acc[mi][ni], ah[mi], bh[ni]);
                }
        }
        __syncthreads();
    }

    // epilogue
#pragma unroll
    for (int mi = 0; mi < 4; mi++) {
#pragma unroll
        for (int ni = 0; ni < 4; ni++) {
            const int r0 = bm * 128 + mwarp + mi * 16 + g;
            const int c  = bn * 128 + nwarp + ni * 8 + 2 * tg;
            const float2 bb = *(const float2*)&bias[c];
            float2 o0 = make_float2(acc[mi][ni][0] + bb.x, acc[mi][ni][1] + bb.y);
            float2 o1 = make_float2(acc[mi][ni][2] + bb.x, acc[mi][ni][3] + bb.y);
            if (res) {
                const float2 r0v = *(const float2*)&res[(size_t)r0 * ldc + c];
                const float2 r1v = *(const float2*)&res[(size_t)(r0 + 8) * ldc + c];
                o0.x += r0v.x; o0.y += r0v.y;
                o1.x += r1v.x; o1.y += r1v.y;
            }
            *(float2*)&C[(size_t)r0 * ldc + c]       = o0;
            *(float2*)&C[(size_t)(r0 + 8) * ldc + c] = o1;
        }
    }
}

// ---------------- Flash attention fp32 w/ packed f32x2 FMA --------------------
// grid (SEQ/64, NHEADS, NB), 64 threads.
__global__ void __launch_bounds__(64) attn_kernel(const float* __restrict__ q,
                                                  const float* __restrict__ k,
                                                  const float* __restrict__ v,
                                                  const float* __restrict__ mask,
                                                  float* __restrict__ ctx)
{
    const int qt = blockIdx.x, head = blockIdx.y, b = blockIdx.z;
    const int t = threadIdx.x;
    __shared__ float Ks[32][64];
    __shared__ float Vs[32][64];
    __shared__ float Msk[32];

    const size_t qrow = (size_t)(b * SEQ + qt * 64 + t);
    const u64* qp = (const u64*)(q + qrow * HD + head * DHEAD);
    u64 q2[32];
#pragma unroll
    for (int i = 0; i < 32; i++) q2[i] = qp[i];
    u64 o2[32];
#pragma unroll
    for (int i = 0; i < 32; i++) o2[i] = 0ull;
    float m = -1e30f, l = 0.f;

    for (int kt = 0; kt < SEQ / 32; kt++) {
        __syncthreads();
        {
            const int r = t >> 1, half = t & 1;
            const size_t krow = (size_t)(b * SEQ + kt * 32 + r);
            const float4* kp = (const float4*)(k + krow * HD + head * DHEAD) + half * 8;
            const float4* vp = (const float4*)(v + krow * HD + head * DHEAD) + half * 8;
            float4* kd = (float4*)&Ks[r][half * 32];
            float4* vd = (float4*)&Vs[r][half * 32];
#pragma unroll
            for (int i = 0; i < 8; i++) { kd[i] = kp[i]; vd[i] = vp[i]; }
            if (t < 32) Msk[t] = -1000.f * (1.f - mask[b * SEQ + kt * 32 + t]);
        }
        __syncthreads();

        float s[32];
#pragma unroll 2
        for (int j = 0; j < 32; j++) {
            const u64* kr = (const u64*)Ks[j];
            u64 aa = 0ull, bb = 0ull;
#pragma unroll
            for (int d = 0; d < 16; d++) {
                aa = fma2(q2[2 * d],     kr[2 * d],     aa);
                bb = fma2(q2[2 * d + 1], kr[2 * d + 1], bb);
            }
            const float2 fa = unpk2(aa), fb = unpk2(bb);
            s[j] = (fa.x + fa.y + fb.x + fb.y) * 0.125f + Msk[j];
        }
        float mt = m;
#pragma unroll
        for (int j = 0; j < 32; j++) mt = fmaxf(mt, s[j]);
        const float corr = __expf(m - mt);
        const u64 corr2 = pk2(corr, corr);
        l *= corr;
#pragma unroll
        for (int i = 0; i < 32; i++) o2[i] = mul2(o2[i], corr2);
#pragma unroll 4
        for (int j = 0; j < 32; j++) {
            const float p = __expf(s[j] - mt);
            l += p;
            const u64 p2 = pk2(p, p);
            const u64* vr = (const u64*)Vs[j];
#pragma unroll
            for (int d = 0; d < 32; d++) o2[d] = fma2(p2, vr[d], o2[d]);
        }
        m = mt;
    }

    const float inv = 1.f / l;
    const u64 inv2 = pk2(inv, inv);
    u64* op = (u64*)(ctx + qrow * HD + head * DHEAD);
#pragma unroll
    for (int i = 0; i < 32; i++) op[i] = mul2(o2[i], inv2);
}

// ---------------- top-k over 256 sign-pattern logits: 1 warp per (n,t) -------
__global__ void __launch_bounds__(256) topk_kernel(const float* __restrict__ hs,
                                                   float* __restrict__ wout,
                                                   int* __restrict__ iout)
{
    const int warp = (blockIdx.x * blockDim.x + threadIdx.x) >> 5;
    const int lane = threadIdx.x & 31;
    const float* hp = hs + (size_t)warp * 8;
    float h[8];
#pragma unroll
    for (int i = 0; i < 8; i++) h[i] = hp[i];

    float lg[8];
#pragma unroll
    for (int i = 0; i < 8; i++) {
        const int c = lane * 8 + i;
        float acc = 0.f;
#pragma unroll
        for (int bb = 0; bb < 8; bb++)
            acc += ((c >> bb) & 1) ? h[bb] : -h[bb];
        lg[i] = acc;
    }

    float m0 = 0.f, sum = 0.f, myv = 0.f;
    int myc = 0;
#pragma unroll
    for (int it = 0; it < 8; it++) {
        float lv = -1e30f;
        int lc = 0;
#pragma unroll
        for (int i = 0; i < 8; i++)
            if (lg[i] > lv) { lv = lg[i]; lc = lane * 8 + i; }
#pragma unroll
        for (int off = 16; off; off >>= 1) {
            const float ov = __shfl_down_sync(0xffffffffu, lv, off);
            const int   oc = __shfl_down_sync(0xffffffffu, lc, off);
            if (ov > lv || (ov == lv && oc < lc)) { lv = ov; lc = oc; }
        }
        lv = __shfl_sync(0xffffffffu, lv, 0);
        lc = __shfl_sync(0xffffffffu, lc, 0);
        if (it == 0) m0 = lv;
        sum += __expf(lv - m0);
        if (lane == it) { myv = lv; myc = lc; }
        if (lane == (lc >> 3)) {
            const int ii = lc & 7;
#pragma unroll
            for (int i = 0; i < 8; i++)
                if (i == ii) lg[i] = -1e30f;
        }
    }
    if (lane < 8) {
        wout[(size_t)warp * 8 + lane] = __expf(myv - m0) / sum;
        iout[(size_t)warp * 8 + lane] = myc;
    }
}

// ---------------- gather FFN (bf16 tables) + residual: 1 block per token ------
__global__ void __launch_bounds__(256) ffn_kernel(const __nv_bfloat16* __restrict__ tables,
                                                  const float* __restrict__ tbias,
                                                  const float* __restrict__ attn,
                                                  const float* __restrict__ wbuf,
                                                  const int* __restrict__ ibuf,
                                                  float* __restrict__ out)
{
    const int n = blockIdx.x;
    const int tid = threadIdx.x;
    __shared__ float sw[512];
    __shared__ int   si[512];
    sw[tid]       = wbuf[(size_t)n * 512 + tid];
    sw[tid + 256] = wbuf[(size_t)n * 512 + 256 + tid];
    si[tid]       = ibuf[(size_t)n * 512 + tid];
    si[tid + 256] = ibuf[(size_t)n * 512 + 256 + tid];
    __syncthreads();

    float4 acc = make_float4(0.f, 0.f, 0.f, 0.f);
    const int hb = tid * 4;
#pragma unroll 4
    for (int p = 0; p < 512; p++) {
        const int tt = p >> 3;
        const uint2 raw = *(const uint2*)&tables[((size_t)tt * TSZ + si[p]) * HD + hb];
        const float2 r0 = __bfloat1622float2(*(const __nv_bfloat162*)&raw.x);
        const float2 r1 = __bfloat1622float2(*(const __nv_bfloat162*)&raw.y);
        const float wv = sw[p];
        acc.x += wv * r0.x; acc.y += wv * r0.y;
        acc.z += wv * r1.x; acc.w += wv * r1.y;
    }
    const float4 bb = *(const float4*)&tbias[hb];
    const float4 aa = *(const float4*)&attn[(size_t)n * HD + hb];
    float4 o;
    o.x = acc.x + bb.x + aa.x;
    o.y = acc.y + bb.y + aa.y;
    o.z = acc.z + bb.z + aa.z;
    o.w = acc.w + bb.w + aa.w;
    *(float4*)&out[(size_t)n * HD + hb] = o;
}

// ---------------- launcher ----------------------------------------------------
extern "C" void kernel_launch(void* const* d_in, const int* in_sizes, int n_in,
                              void* d_out, int out_size)
{
    const float* hidden = (const float*)d_in[0];
    const float* amask  = (const float*)d_in[1];
    const float* ln1g   = (const float*)d_in[2];
    const float* ln1b   = (const float*)d_in[3];
    const float* Wq     = (const float*)d_in[4];
    const float* bq     = (const float*)d_in[5];
    const float* Wk     = (const float*)d_in[6];
    const float* bk     = (const float*)d_in[7];
    const float* Wv     = (const float*)d_in[8];
    const float* bv     = (const float*)d_in[9];
    const float* Wo     = (const float*)d_in[10];
    const float* bo     = (const float*)d_in[11];
    const float* ln2g   = (const float*)d_in[12];
    const float* ln2b   = (const float*)d_in[13];
    const float* Wh     = (const float*)d_in[14];
    const float* bh     = (const float*)d_in[15];
    const float* tw     = (const float*)d_in[16];
    const float* tb     = (const float*)d_in[17];
    float* out = (float*)d_out;

    float *x, *q, *k, *v, *ctx, *attn, *y, *hsb, *wb;
    __nv_bfloat16* tbl;
    int* ib;
    cudaGetSymbolAddress((void**)&x,    g_x);
    cudaGetSymbolAddress((void**)&q,    g_q);
    cudaGetSymbolAddress((void**)&k,    g_k);
    cudaGetSymbolAddress((void**)&v,    g_v);
    cudaGetSymbolAddress((void**)&ctx,  g_ctx);
    cudaGetSymbolAddress((void**)&attn, g_attn);
    cudaGetSymbolAddress((void**)&y,    g_y);
    cudaGetSymbolAddress((void**)&hsb,  g_hs);
    cudaGetSymbolAddress((void**)&wb,   g_w);
    cudaGetSymbolAddress((void**)&ib,   g_i);
    cudaGetSymbolAddress((void**)&tbl,  g_tbl);

    // 0. convert tables to bf16 (error negligible: ffn term ~2% of output)
    tbl_bf16_kernel<<<(TT * TSZ * HD) / (256 * 8), 256>>>(tw, tbl);

    // 1. LN1
    ln_kernel<<<NTOK, 256>>>(hidden, ln1g, ln1b, x);

    // 2. QKV projections (3xTF32 tensor cores, ~fp32 precision)
    dim3 gqkv(HD / 128, NTOK / 128);
    gemm_tf32_kernel<<<gqkv, 256>>>(x, Wq, bq, nullptr, q, HD, HD, HD);
    gemm_tf32_kernel<<<gqkv, 256>>>(x, Wk, bk, nullptr, k, HD, HD, HD);
    gemm_tf32_kernel<<<gqkv, 256>>>(x, Wv, bv, nullptr, v, HD, HD, HD);

    // 3. attention (f32x2 packed FMA, exact fp32)
    attn_kernel<<<dim3(SEQ / 64, NHEADS, NB), 64>>>(q, k, v, amask, ctx);

    // 4. output projection + residual
    gemm_tf32_kernel<<<gqkv, 256>>>(ctx, Wo, bo, hidden, attn, HD, HD, HD);

    // 5. LN2
    ln_kernel<<<NTOK, 256>>>(attn, ln2g, ln2b, y);

    // 6. table-head projection (first 512 cols of Wh)
    gemm_tf32_kernel<<<dim3(512 / 128, NTOK / 128), 256>>>(y, Wh, bh, nullptr, hsb, HD, HD, 512);

    // 7. sign-pattern logits + top-8 + softmax weights
    topk_kernel<<<(NTOK * TT) / 8, 256>>>(hsb, wb, ib);

    // 8. gather FFN (bf16 tables) + bias + attn residual -> out
    ffn_kernel<<<NTOK, 256>>>(tbl, tb, attn, wb, ib, out);
}

// round 6
// speedup vs baseline: 1.5881x; 1.5630x over previous
#include <cuda_runtime.h>
#include <cuda_bf16.h>
#include <cstdint>
#include <cstddef>

#define HD   1024
#define NHEADS 16
#define DHEAD  64
#define TT     64
#define TSZ   256
#define NBITS   8
#define KSEL    8
#define NTOK 4096
#define SEQ  2048
#define NB      2

typedef unsigned long long u64;

// ---------------- scratch (static device globals; no allocs allowed) ----------
__device__ float g_x   [NTOK * HD];
__device__ float g_q   [NTOK * HD];
__device__ float g_k   [NTOK * HD];
__device__ float g_v   [NTOK * HD];
__device__ float g_ctx [NTOK * HD];
__device__ float g_attn[NTOK * HD];
__device__ float g_y   [NTOK * HD];
__device__ float g_hs  [NTOK * TT * NBITS];
__device__ float g_w   [NTOK * TT * KSEL];
__device__ int   g_i   [NTOK * TT * KSEL];
__device__ __nv_bfloat16 g_tbl[TT * TSZ * HD];

// ---------------- small helpers ----------------------------------------------
__device__ __forceinline__ float tf32r(float x) {
    uint32_t r;
    asm("cvt.rna.tf32.f32 %0, %1;" : "=r"(r) : "f"(x));
    return __uint_as_float(r);
}
__device__ __forceinline__ uint32_t tf32b(float x) {
    uint32_t r;
    asm("cvt.rna.tf32.f32 %0, %1;" : "=r"(r) : "f"(x));
    return r;
}
__device__ __forceinline__ void split_tf32(float x, uint32_t& hi, uint32_t& lo) {
    const float h = tf32r(x);
    hi = __float_as_uint(h);
    lo = __float_as_uint(tf32r(x - h));
}
__device__ __forceinline__ void mma_tf32(float* acc, const uint32_t* a, const uint32_t* b) {
    asm volatile(
        "mma.sync.aligned.m16n8k8.row.col.f32.tf32.tf32.f32 "
        "{%0,%1,%2,%3}, {%4,%5,%6,%7}, {%8,%9}, {%0,%1,%2,%3};\n"
        : "+f"(acc[0]), "+f"(acc[1]), "+f"(acc[2]), "+f"(acc[3])
        : "r"(a[0]), "r"(a[1]), "r"(a[2]), "r"(a[3]), "r"(b[0]), "r"(b[1]));
}

// ---------------- fp32 -> bf16 table conversion -------------------------------
__global__ void __launch_bounds__(256) tbl_bf16_kernel(const float* __restrict__ in,
                                                       __nv_bfloat16* __restrict__ out)
{
    const size_t i = ((size_t)blockIdx.x * 256 + threadIdx.x) * 8;
    const float4 a = *(const float4*)(in + i);
    const float4 b = *(const float4*)(in + i + 4);
    __nv_bfloat162 p0 = __float22bfloat162_rn(make_float2(a.x, a.y));
    __nv_bfloat162 p1 = __float22bfloat162_rn(make_float2(a.z, a.w));
    __nv_bfloat162 p2 = __float22bfloat162_rn(make_float2(b.x, b.y));
    __nv_bfloat162 p3 = __float22bfloat162_rn(make_float2(b.z, b.w));
    uint4 o;
    o.x = *(uint32_t*)&p0; o.y = *(uint32_t*)&p1;
    o.z = *(uint32_t*)&p2; o.w = *(uint32_t*)&p3;
    *(uint4*)(out + i) = o;
}

// ---------------- LayerNorm: one block per row of 1024 ------------------------
__global__ void __launch_bounds__(256) ln_kernel(const float* __restrict__ in,
                                                 const float* __restrict__ gamma,
                                                 const float* __restrict__ beta,
                                                 float* __restrict__ out)
{
    const int row = blockIdx.x;
    const int tid = threadIdx.x;
    const float4 v = *(const float4*)(in + (size_t)row * HD + tid * 4);
    float s  = v.x + v.y + v.z + v.w;
    float sq = v.x * v.x + v.y * v.y + v.z * v.z + v.w * v.w;

    __shared__ float rs[8], rq[8];
    __shared__ float smean, sinv;
    const int lane = tid & 31, wid = tid >> 5;
#pragma unroll
    for (int off = 16; off; off >>= 1) {
        s  += __shfl_down_sync(0xffffffffu, s,  off);
        sq += __shfl_down_sync(0xffffffffu, sq, off);
    }
    if (lane == 0) { rs[wid] = s; rq[wid] = sq; }
    __syncthreads();
    if (tid == 0) {
        float ts = 0.f, tq = 0.f;
#pragma unroll
        for (int i = 0; i < 8; i++) { ts += rs[i]; tq += rq[i]; }
        const float mean = ts * (1.f / HD);
        const float var  = tq * (1.f / HD) - mean * mean;
        smean = mean;
        sinv  = rsqrtf(var + 1e-12f);
    }
    __syncthreads();
    const float mean = smean, inv = sinv;
    const float4 gv = *(const float4*)(gamma + tid * 4);
    const float4 bv = *(const float4*)(beta  + tid * 4);
    float4 o;
    o.x = (v.x - mean) * inv * gv.x + bv.x;
    o.y = (v.y - mean) * inv * gv.y + bv.y;
    o.z = (v.z - mean) * inv * gv.z + bv.z;
    o.w = (v.w - mean) * inv * gv.w + bv.w;
    *(float4*)(out + (size_t)row * HD + tid * 4) = o;
}

// ---------------- 3xTF32 tensor-core GEMM 128x128x32, 8 warps ----------------
// (unchanged from R5 — known correct)
__global__ void __launch_bounds__(256) gemm_tf32_kernel(const float* __restrict__ A,
                                                        const float* __restrict__ B,
                                                        const float* __restrict__ bias,
                                                        const float* __restrict__ res,
                                                        float* __restrict__ C,
                                                        int Kd, int ldb, int ldc)
{
    __shared__ float As[128][36];
    __shared__ float Bs[32][136];

    const int tid  = threadIdx.x;
    const int wrp  = tid >> 5;
    const int lane = tid & 31;
    const int g  = lane >> 2;
    const int tg = lane & 3;
    const int bm = blockIdx.y, bn = blockIdx.x;
    const int mwarp = (wrp >> 2) * 64;
    const int nwarp = (wrp & 3) * 32;

    const int arow = tid >> 1, acol = (tid & 1) * 16;
    const int brow = tid >> 3, bcol = (tid & 7) * 16;
    const float* Ap = A + (size_t)(bm * 128 + arow) * Kd + acol;
    const float* Bp = B + (size_t)brow * ldb + bn * 128 + bcol;

    float acc[4][4][4];
#pragma unroll
    for (int mi = 0; mi < 4; mi++)
#pragma unroll
        for (int ni = 0; ni < 4; ni++)
#pragma unroll
            for (int c = 0; c < 4; c++) acc[mi][ni][c] = 0.f;

    for (int k0 = 0; k0 < Kd; k0 += 32) {
#pragma unroll
        for (int i = 0; i < 4; i++) {
            const float4 av = *(const float4*)(Ap + i * 4);
            *(float4*)&As[arow][acol + i * 4] = av;
            const float4 bv = *(const float4*)(Bp + i * 4);
            *(float4*)&Bs[brow][bcol + i * 4] = bv;
        }
        Ap += 32;
        Bp += (size_t)32 * ldb;
        __syncthreads();

#pragma unroll
        for (int ks = 0; ks < 4; ks++) {
            const int kk = ks * 8;
            uint32_t ah[4][4], al[4][4], bh[4][2], bl[4][2];
#pragma unroll
            for (int mi = 0; mi < 4; mi++) {
                const float* pa  = &As[mwarp + mi * 16 + g][kk + tg];
                const float* pa8 = pa + 8 * 36;
                split_tf32(pa[0],  ah[mi][0], al[mi][0]);
                split_tf32(pa8[0], ah[mi][1], al[mi][1]);
                split_tf32(pa[4],  ah[mi][2], al[mi][2]);
                split_tf32(pa8[4], ah[mi][3], al[mi][3]);
            }
#pragma unroll
            for (int ni = 0; ni < 4; ni++) {
                const float* pb = &Bs[kk + tg][nwarp + ni * 8 + g];
                split_tf32(pb[0],       bh[ni][0], bl[ni][0]);
                split_tf32(pb[4 * 136], bh[ni][1], bl[ni][1]);
            }
#pragma unroll
            for (int mi = 0; mi < 4; mi++)
#pragma unroll
                for (int ni = 0; ni < 4; ni++) {
                    mma_tf32(acc[mi][ni], al[mi], bh[ni]);
                    mma_tf32(acc[mi][ni], ah[mi], bl[ni]);
                    mma_tf32(acc[mi][ni], ah[mi], bh[ni]);
                }
        }
        __syncthreads();
    }

#pragma unroll
    for (int mi = 0; mi < 4; mi++) {
#pragma unroll
        for (int ni = 0; ni < 4; ni++) {
            const int r0 = bm * 128 + mwarp + mi * 16 + g;
            const int c  = bn * 128 + nwarp + ni * 8 + 2 * tg;
            const float2 bb = *(const float2*)&bias[c];
            float2 o0 = make_float2(acc[mi][ni][0] + bb.x, acc[mi][ni][1] + bb.y);
            float2 o1 = make_float2(acc[mi][ni][2] + bb.x, acc[mi][ni][3] + bb.y);
            if (res) {
                const float2 r0v = *(const float2*)&res[(size_t)r0 * ldc + c];
                const float2 r1v = *(const float2*)&res[(size_t)(r0 + 8) * ldc + c];
                o0.x += r0v.x; o0.y += r0v.y;
                o1.x += r1v.x; o1.y += r1v.y;
            }
            *(float2*)&C[(size_t)r0 * ldc + c]       = o0;
            *(float2*)&C[(size_t)(r0 + 8) * ldc + c] = o1;
        }
    }
}

// ---------------- MMA flash attention (tf32 tensor cores) ---------------------
// grid (SEQ/64, NHEADS, NB), 128 threads (4 warps). Warp w owns q rows 16w..16w+15.
// KV tiles of 64 rows. S = Q@K^T via m16n8k8; fp32 online softmax in regs;
// P round-trips smem (aliased with K tile) as tf32; O += P@V via m16n8k8.
__global__ void __launch_bounds__(128) attn_mma_kernel(const float* __restrict__ q,
                                                       const float* __restrict__ k,
                                                       const float* __restrict__ v,
                                                       const float* __restrict__ mask,
                                                       float* __restrict__ ctx)
{
    const int qt = blockIdx.x, head = blockIdx.y, b = blockIdx.z;
    const int tid  = threadIdx.x;
    const int w    = tid >> 5;
    const int lane = tid & 31;
    const int g    = lane >> 2;   // groupID (row within frag)
    const int tg   = lane & 3;    // thread in group (col within frag)

    __shared__ float KsPs[64][68];   // K tile during S phase; P tile during PV phase
    __shared__ float Vs[64][72];
    __shared__ float Msk[64];

    // ---- Q fragments (tf32), loaded once -------------------------------------
    const size_t q0 = (size_t)(b * SEQ + qt * 64 + 16 * w) * HD + head * DHEAD;
    uint32_t qa[8][4];
#pragma unroll
    for (int kj = 0; kj < 8; kj++) {
        const int c = 8 * kj + tg;
        qa[kj][0] = tf32b(q[q0 + (size_t)g * HD + c]);
        qa[kj][1] = tf32b(q[q0 + (size_t)(g + 8) * HD + c]);
        qa[kj][2] = tf32b(q[q0 + (size_t)g * HD + c + 4]);
        qa[kj][3] = tf32b(q[q0 + (size_t)(g + 8) * HD + c + 4]);
    }

    float oacc[8][4];
#pragma unroll
    for (int di = 0; di < 8; di++)
#pragma unroll
        for (int c = 0; c < 4; c++) oacc[di][c] = 0.f;
    float m0 = -1e30f, m1 = -1e30f, l0 = 0.f, l1 = 0.f;

    const int r  = tid >> 1;           // K/V load row 0..63
    const int cb = (tid & 1) * 32;     // col half

    for (int kt = 0; kt < SEQ / 64; kt++) {
        __syncthreads();  // previous tile fully consumed (Ps reads + Vs reads)
        // ---- load K,V tile (tf32-rounded) ------------------------------------
        {
            const size_t kvrow = (size_t)(b * SEQ + kt * 64 + r) * HD + head * DHEAD + cb;
            const float4* kp = (const float4*)(k + kvrow);
            const float4* vp = (const float4*)(v + kvrow);
#pragma unroll
            for (int i = 0; i < 8; i++) {
                float4 kv4 = kp[i];
                kv4.x = tf32r(kv4.x); kv4.y = tf32r(kv4.y);
                kv4.z = tf32r(kv4.z); kv4.w = tf32r(kv4.w);
                *(float4*)&KsPs[r][cb + 4 * i] = kv4;
                float4 vv4 = vp[i];
                vv4.x = tf32r(vv4.x); vv4.y = tf32r(vv4.y);
                vv4.z = tf32r(vv4.z); vv4.w = tf32r(vv4.w);
                *(float4*)&Vs[r][cb + 4 * i] = vv4;
            }
            if (tid < 64) Msk[tid] = -1000.f * (1.f - mask[b * SEQ + kt * 64 + tid]);
        }
        __syncthreads();

        // ---- S = Q @ K^T -----------------------------------------------------
        float sacc[8][4];
#pragma unroll
        for (int ni = 0; ni < 8; ni++) {
            sacc[ni][0] = sacc[ni][1] = sacc[ni][2] = sacc[ni][3] = 0.f;
#pragma unroll
            for (int kj = 0; kj < 8; kj++) {
                uint32_t bb[2];
                bb[0] = __float_as_uint(KsPs[8 * ni + g][8 * kj + tg]);
                bb[1] = __float_as_uint(KsPs[8 * ni + g][8 * kj + tg + 4]);
                mma_tf32(sacc[ni], qa[kj], bb);
            }
        }
        // scale + mask
#pragma unroll
        for (int ni = 0; ni < 8; ni++) {
            const int c0 = 8 * ni + 2 * tg;
            sacc[ni][0] = sacc[ni][0] * 0.125f + Msk[c0];
            sacc[ni][1] = sacc[ni][1] * 0.125f + Msk[c0 + 1];
            sacc[ni][2] = sacc[ni][2] * 0.125f + Msk[c0];
            sacc[ni][3] = sacc[ni][3] * 0.125f + Msk[c0 + 1];
        }
        // ---- online softmax (rows g and g+8) ---------------------------------
        float t0 = -1e30f, t1 = -1e30f;
#pragma unroll
        for (int ni = 0; ni < 8; ni++) {
            t0 = fmaxf(t0, fmaxf(sacc[ni][0], sacc[ni][1]));
            t1 = fmaxf(t1, fmaxf(sacc[ni][2], sacc[ni][3]));
        }
        t0 = fmaxf(t0, __shfl_xor_sync(0xffffffffu, t0, 1));
        t0 = fmaxf(t0, __shfl_xor_sync(0xffffffffu, t0, 2));
        t1 = fmaxf(t1, __shfl_xor_sync(0xffffffffu, t1, 1));
        t1 = fmaxf(t1, __shfl_xor_sync(0xffffffffu, t1, 2));
        const float nm0 = fmaxf(m0, t0), nm1 = fmaxf(m1, t1);
        const float cr0 = __expf(m0 - nm0), cr1 = __expf(m1 - nm1);
        m0 = nm0; m1 = nm1;
        float ls0 = 0.f, ls1 = 0.f;
#pragma unroll
        for (int ni = 0; ni < 8; ni++) {
            sacc[ni][0] = __expf(sacc[ni][0] - nm0);
            sacc[ni][1] = __expf(sacc[ni][1] - nm0);
            sacc[ni][2] = __expf(sacc[ni][2] - nm1);
            sacc[ni][3] = __expf(sacc[ni][3] - nm1);
            ls0 += sacc[ni][0] + sacc[ni][1];
            ls1 += sacc[ni][2] + sacc[ni][3];
        }
        ls0 += __shfl_xor_sync(0xffffffffu, ls0, 1);
        ls0 += __shfl_xor_sync(0xffffffffu, ls0, 2);
        ls1 += __shfl_xor_sync(0xffffffffu, ls1, 1);
        ls1 += __shfl_xor_sync(0xffffffffu, ls1, 2);
        l0 = l0 * cr0 + ls0;
        l1 = l1 * cr1 + ls1;
#pragma unroll
        for (int di = 0; di < 8; di++) {
            oacc[di][0] *= cr0; oacc[di][1] *= cr0;
            oacc[di][2] *= cr1; oacc[di][3] *= cr1;
        }
        // ---- store P (tf32) into KsPs (K no longer needed) -------------------
        __syncthreads();   // all warps done reading K tile
#pragma unroll
        for (int ni = 0; ni < 8; ni++) {
            const int c0 = 8 * ni + 2 * tg;
            float2 p0 = make_float2(tf32r(sacc[ni][0]), tf32r(sacc[ni][1]));
            float2 p1 = make_float2(tf32r(sacc[ni][2]), tf32r(sacc[ni][3]));
            *(float2*)&KsPs[16 * w + g][c0]     = p0;
            *(float2*)&KsPs[16 * w + g + 8][c0] = p1;
        }
        __syncwarp();      // P visible within warp (warps own disjoint row sets)

        // ---- O += P @ V ------------------------------------------------------
#pragma unroll
        for (int kj = 0; kj < 8; kj++) {
            uint32_t pa[4];
            const int c = 8 * kj + tg;
            pa[0] = __float_as_uint(KsPs[16 * w + g][c]);
            pa[1] = __float_as_uint(KsPs[16 * w + g + 8][c]);
            pa[2] = __float_as_uint(KsPs[16 * w + g][c + 4]);
            pa[3] = __float_as_uint(KsPs[16 * w + g + 8][c + 4]);
#pragma unroll
            for (int di = 0; di < 8; di++) {
                uint32_t bb[2];
                bb[0] = __float_as_uint(Vs[8 * kj + tg][8 * di + g]);
                bb[1] = __float_as_uint(Vs[8 * kj + tg + 4][8 * di + g]);
                mma_tf32(oacc[di], pa, bb);
            }
        }
    }

    // ---- epilogue: O / l -> ctx ----------------------------------------------
    const float i0 = 1.f / l0, i1 = 1.f / l1;
    const size_t o0 = (size_t)(b * SEQ + qt * 64 + 16 * w) * HD + head * DHEAD;
#pragma unroll
    for (int di = 0; di < 8; di++) {
        const int c = 8 * di + 2 * tg;
        float2 r0v = make_float2(oacc[di][0] * i0, oacc[di][1] * i0);
        float2 r1v = make_float2(oacc[di][2] * i1, oacc[di][3] * i1);
        *(float2*)&ctx[o0 + (size_t)g * HD + c]       = r0v;
        *(float2*)&ctx[o0 + (size_t)(g + 8) * HD + c] = r1v;
    }
}

// ---------------- top-k over 256 sign-pattern logits: 1 warp per (n,t) -------
__global__ void __launch_bounds__(256) topk_kernel(const float* __restrict__ hs,
                                                   float* __restrict__ wout,
                                                   int* __restrict__ iout)
{
    const int warp = (blockIdx.x * blockDim.x + threadIdx.x) >> 5;
    const int lane = threadIdx.x & 31;
    const float* hp = hs + (size_t)warp * 8;
    float h[8];
#pragma unroll
    for (int i = 0; i < 8; i++) h[i] = hp[i];

    float lg[8];
#pragma unroll
    for (int i = 0; i < 8; i++) {
        const int c = lane * 8 + i;
        float acc = 0.f;
#pragma unroll
        for (int bb = 0; bb < 8; bb++)
            acc += ((c >> bb) & 1) ? h[bb] : -h[bb];
        lg[i] = acc;
    }

    float m0 = 0.f, sum = 0.f, myv = 0.f;
    int myc = 0;
#pragma unroll
    for (int it = 0; it < 8; it++) {
        float lv = -1e30f;
        int lc = 0;
#pragma unroll
        for (int i = 0; i < 8; i++)
            if (lg[i] > lv) { lv = lg[i]; lc = lane * 8 + i; }
#pragma unroll
        for (int off = 16; off; off >>= 1) {
            const float ov = __shfl_down_sync(0xffffffffu, lv, off);
            const int   oc = __shfl_down_sync(0xffffffffu, lc, off);
            if (ov > lv || (ov == lv && oc < lc)) { lv = ov; lc = oc; }
        }
        lv = __shfl_sync(0xffffffffu, lv, 0);
        lc = __shfl_sync(0xffffffffu, lc, 0);
        if (it == 0) m0 = lv;
        sum += __expf(lv - m0);
        if (lane == it) { myv = lv; myc = lc; }
        if (lane == (lc >> 3)) {
            const int ii = lc & 7;
#pragma unroll
            for (int i = 0; i < 8; i++)
                if (i == ii) lg[i] = -1e30f;
        }
    }
    if (lane < 8) {
        wout[(size_t)warp * 8 + lane] = __expf(myv - m0) / sum;
        iout[(size_t)warp * 8 + lane] = myc;
    }
}

// ---------------- gather FFN (bf16 tables) + residual: 1 block per token ------
__global__ void __launch_bounds__(256) ffn_kernel(const __nv_bfloat16* __restrict__ tables,
                                                  const float* __restrict__ tbias,
                                                  const float* __restrict__ attn,
                                                  const float* __restrict__ wbuf,
                                                  const int* __restrict__ ibuf,
                                                  float* __restrict__ out)
{
    const int n = blockIdx.x;
    const int tid = threadIdx.x;
    __shared__ float sw[512];
    __shared__ int   si[512];
    sw[tid]       = wbuf[(size_t)n * 512 + tid];
    sw[tid + 256] = wbuf[(size_t)n * 512 + 256 + tid];
    si[tid]       = ibuf[(size_t)n * 512 + tid];
    si[tid + 256] = ibuf[(size_t)n * 512 + 256 + tid];
    __syncthreads();

    float4 acc = make_float4(0.f, 0.f, 0.f, 0.f);
    const int hb = tid * 4;
#pragma unroll 4
    for (int p = 0; p < 512; p++) {
        const int tt = p >> 3;
        const uint2 raw = *(const uint2*)&tables[((size_t)tt * TSZ + si[p]) * HD + hb];
        const float2 r0 = __bfloat1622float2(*(const __nv_bfloat162*)&raw.x);
        const float2 r1 = __bfloat1622float2(*(const __nv_bfloat162*)&raw.y);
        const float wv = sw[p];
        acc.x += wv * r0.x; acc.y += wv * r0.y;
        acc.z += wv * r1.x; acc.w += wv * r1.y;
    }
    const float4 bb = *(const float4*)&tbias[hb];
    const float4 aa = *(const float4*)&attn[(size_t)n * HD + hb];
    float4 o;
    o.x = acc.x + bb.x + aa.x;
    o.y = acc.y + bb.y + aa.y;
    o.z = acc.z + bb.z + aa.z;
    o.w = acc.w + bb.w + aa.w;
    *(float4*)&out[(size_t)n * HD + hb] = o;
}

// ---------------- launcher ----------------------------------------------------
extern "C" void kernel_launch(void* const* d_in, const int* in_sizes, int n_in,
                              void* d_out, int out_size)
{
    const float* hidden = (const float*)d_in[0];
    const float* amask  = (const float*)d_in[1];
    const float* ln1g   = (const float*)d_in[2];
    const float* ln1b   = (const float*)d_in[3];
    const float* Wq     = (const float*)d_in[4];
    const float* bq     = (const float*)d_in[5];
    const float* Wk     = (const float*)d_in[6];
    const float* bk     = (const float*)d_in[7];
    const float* Wv     = (const float*)d_in[8];
    const float* bv     = (const float*)d_in[9];
    const float* Wo     = (const float*)d_in[10];
    const float* bo     = (const float*)d_in[11];
    const float* ln2g   = (const float*)d_in[12];
    const float* ln2b   = (const float*)d_in[13];
    const float* Wh     = (const float*)d_in[14];
    const float* bh     = (const float*)d_in[15];
    const float* tw     = (const float*)d_in[16];
    const float* tb     = (const float*)d_in[17];
    float* out = (float*)d_out;

    float *x, *q, *k, *v, *ctx, *attn, *y, *hsb, *wb;
    __nv_bfloat16* tbl;
    int* ib;
    cudaGetSymbolAddress((void**)&x,    g_x);
    cudaGetSymbolAddress((void**)&q,    g_q);
    cudaGetSymbolAddress((void**)&k,    g_k);
    cudaGetSymbolAddress((void**)&v,    g_v);
    cudaGetSymbolAddress((void**)&ctx,  g_ctx);
    cudaGetSymbolAddress((void**)&attn, g_attn);
    cudaGetSymbolAddress((void**)&y,    g_y);
    cudaGetSymbolAddress((void**)&hsb,  g_hs);
    cudaGetSymbolAddress((void**)&wb,   g_w);
    cudaGetSymbolAddress((void**)&ib,   g_i);
    cudaGetSymbolAddress((void**)&tbl,  g_tbl);

    // 0. convert tables to bf16
    tbl_bf16_kernel<<<(TT * TSZ * HD) / (256 * 8), 256>>>(tw, tbl);

    // 1. LN1
    ln_kernel<<<NTOK, 256>>>(hidden, ln1g, ln1b, x);

    // 2. QKV projections (3xTF32 tensor cores)
    dim3 gqkv(HD / 128, NTOK / 128);
    gemm_tf32_kernel<<<gqkv, 256>>>(x, Wq, bq, nullptr, q, HD, HD, HD);
    gemm_tf32_kernel<<<gqkv, 256>>>(x, Wk, bk, nullptr, k, HD, HD, HD);
    gemm_tf32_kernel<<<gqkv, 256>>>(x, Wv, bv, nullptr, v, HD, HD, HD);

    // 3. attention (tf32 MMA flash)
    attn_mma_kernel<<<dim3(SEQ / 64, NHEADS, NB), 128>>>(q, k, v, amask, ctx);

    // 4. output projection + residual
    gemm_tf32_kernel<<<gqkv, 256>>>(ctx, Wo, bo, hidden, attn, HD, HD, HD);

    // 5. LN2
    ln_kernel<<<NTOK, 256>>>(attn, ln2g, ln2b, y);

    // 6. table-head projection (first 512 cols of Wh)
    gemm_tf32_kernel<<<dim3(512 / 128, NTOK / 128), 256>>>(y, Wh, bh, nullptr, hsb, HD, HD, 512);

    // 7. sign-pattern logits + top-8 + softmax weights
    topk_kernel<<<(NTOK * TT) / 8, 256>>>(hsb, wb, ib);

    // 8. gather FFN (bf16 tables) + bias + attn residual -> out
    ffn_kernel<<<NTOK, 256>>>(tbl, tb, attn, wb, ib, out);
}

// round 8
// speedup vs baseline: 1.7616x; 1.1092x over previous
#include <cuda_runtime.h>
#include <cuda_bf16.h>
#include <cstdint>
#include <cstddef>

#define HD   1024
#define NHEADS 16
#define DHEAD  64
#define TT     64
#define TSZ   256
#define NBITS   8
#define KSEL    8
#define NTOK 4096
#define SEQ  2048
#define NB      2

typedef unsigned long long u64;

// ---------------- scratch (static device globals; no allocs allowed) ----------
__device__ float g_x   [NTOK * HD];
__device__ float g_q   [NTOK * HD];
__device__ float g_k   [NTOK * HD];
__device__ float g_v   [NTOK * HD];
__device__ float g_ctx [NTOK * HD];
__device__ float g_attn[NTOK * HD];
__device__ float g_y   [NTOK * HD];
__device__ float g_hs  [NTOK * TT * NBITS];
__device__ float g_w   [NTOK * TT * KSEL];
__device__ int   g_i   [NTOK * TT * KSEL];
__device__ __nv_bfloat16 g_tbl[TT * TSZ * HD];

// ---------------- small helpers ----------------------------------------------
__device__ __forceinline__ float tf32r(float x) {
    uint32_t r;
    asm("cvt.rna.tf32.f32 %0, %1;" : "=r"(r) : "f"(x));
    return __uint_as_float(r);
}
__device__ __forceinline__ uint32_t tf32b(float x) {
    uint32_t r;
    asm("cvt.rna.tf32.f32 %0, %1;" : "=r"(r) : "f"(x));
    return r;
}
__device__ __forceinline__ void mma_tf32(float* acc, const uint32_t* a, const uint32_t* b) {
    asm volatile(
        "mma.sync.aligned.m16n8k8.row.col.f32.tf32.tf32.f32 "
        "{%0,%1,%2,%3}, {%4,%5,%6,%7}, {%8,%9}, {%0,%1,%2,%3};\n"
        : "+f"(acc[0]), "+f"(acc[1]), "+f"(acc[2]), "+f"(acc[3])
        : "r"(a[0]), "r"(a[1]), "r"(a[2]), "r"(a[3]), "r"(b[0]), "r"(b[1]));
}
// split a float4 into tf32 hi/lo float4s and store to smem
__device__ __forceinline__ void split_store4(float4 v, float* hi, float* lo) {
    const float h0 = tf32r(v.x), h1 = tf32r(v.y), h2 = tf32r(v.z), h3 = tf32r(v.w);
    *(float4*)hi = make_float4(h0, h1, h2, h3);
    *(float4*)lo = make_float4(tf32r(v.x - h0), tf32r(v.y - h1),
                               tf32r(v.z - h2), tf32r(v.w - h3));
}

// ---------------- fp32 -> bf16 table conversion -------------------------------
__global__ void __launch_bounds__(256) tbl_bf16_kernel(const float* __restrict__ in,
                                                       __nv_bfloat16* __restrict__ out)
{
    const size_t i = ((size_t)blockIdx.x * 256 + threadIdx.x) * 8;
    const float4 a = *(const float4*)(in + i);
    const float4 b = *(const float4*)(in + i + 4);
    __nv_bfloat162 p0 = __float22bfloat162_rn(make_float2(a.x, a.y));
    __nv_bfloat162 p1 = __float22bfloat162_rn(make_float2(a.z, a.w));
    __nv_bfloat162 p2 = __float22bfloat162_rn(make_float2(b.x, b.y));
    __nv_bfloat162 p3 = __float22bfloat162_rn(make_float2(b.z, b.w));
    uint4 o;
    o.x = *(uint32_t*)&p0; o.y = *(uint32_t*)&p1;
    o.z = *(uint32_t*)&p2; o.w = *(uint32_t*)&p3;
    *(uint4*)(out + i) = o;
}

// ---------------- LayerNorm: one block per row of 1024 ------------------------
__global__ void __launch_bounds__(256) ln_kernel(const float* __restrict__ in,
                                                 const float* __restrict__ gamma,
                                                 const float* __restrict__ beta,
                                                 float* __restrict__ out)
{
    const int row = blockIdx.x;
    const int tid = threadIdx.x;
    const float4 v = *(const float4*)(in + (size_t)row * HD + tid * 4);
    float s  = v.x + v.y + v.z + v.w;
    float sq = v.x * v.x + v.y * v.y + v.z * v.z + v.w * v.w;

    __shared__ float rs[8], rq[8];
    __shared__ float smean, sinv;
    const int lane = tid & 31, wid = tid >> 5;
#pragma unroll
    for (int off = 16; off; off >>= 1) {
        s  += __shfl_down_sync(0xffffffffu, s,  off);
        sq += __shfl_down_sync(0xffffffffu, sq, off);
    }
    if (lane == 0) { rs[wid] = s; rq[wid] = sq; }
    __syncthreads();
    if (tid == 0) {
        float ts = 0.f, tq = 0.f;
#pragma unroll
        for (int i = 0; i < 8; i++) { ts += rs[i]; tq += rq[i]; }
        const float mean = ts * (1.f / HD);
        const float var  = tq * (1.f / HD) - mean * mean;
        smean = mean;
        sinv  = rsqrtf(var + 1e-12f);
    }
    __syncthreads();
    const float mean = smean, inv = sinv;
    const float4 gv = *(const float4*)(gamma + tid * 4);
    const float4 bv = *(const float4*)(beta  + tid * 4);
    float4 o;
    o.x = (v.x - mean) * inv * gv.x + bv.x;
    o.y = (v.y - mean) * inv * gv.y + bv.y;
    o.z = (v.z - mean) * inv * gv.z + bv.z;
    o.w = (v.w - mean) * inv * gv.w + bv.w;
    *(float4*)(out + (size_t)row * HD + tid * 4) = o;
}

// ---------------- 3xTF32 tensor-core GEMM 128x128x16, 8 warps ----------------
// Split-at-smem-store (hi/lo tiles) + register-prefetch pipeline.
__global__ void __launch_bounds__(256) gemm_tf32_kernel(const float* __restrict__ A,
                                                        const float* __restrict__ B,
                                                        const float* __restrict__ bias,
                                                        const float* __restrict__ res,
                                                        float* __restrict__ C,
                                                        int Kd, int ldb, int ldc)
{
    __shared__ float Ah[128][20], Al[128][20];   // [m][k] hi/lo, pitch 20
    __shared__ float Bh[16][136],  Bl[16][136];  // [k][n] hi/lo, pitch 136

    const int tid  = threadIdx.x;
    const int wrp  = tid >> 5;
    const int lane = tid & 31;
    const int g  = lane >> 2;
    const int tg = lane & 3;
    const int bm = blockIdx.y, bn = blockIdx.x;
    const int mwarp = (wrp >> 2) * 64;
    const int nwarp = (wrp & 3) * 32;

    const int arow = tid >> 1, acol = (tid & 1) * 8;
    const int brow = tid >> 4, bcol = (tid & 15) * 8;
    const float* Ap = A + (size_t)(bm * 128 + arow) * Kd + acol;
    const float* Bp = B + (size_t)brow * ldb + bn * 128 + bcol;

    float acc[4][4][4];
#pragma unroll
    for (int mi = 0; mi < 4; mi++)
#pragma unroll
        for (int ni = 0; ni < 4; ni++)
#pragma unroll
            for (int c = 0; c < 4; c++) acc[mi][ni][c] = 0.f;

    // prefetch tile 0
    float4 ra0 = *(const float4*)Ap;
    float4 ra1 = *(const float4*)(Ap + 4);
    float4 rb0 = *(const float4*)Bp;
    float4 rb1 = *(const float4*)(Bp + 4);

    for (int k0 = 0; k0 < Kd; k0 += 16) {
        // split-store current tile
        split_store4(ra0, &Ah[arow][acol],     &Al[arow][acol]);
        split_store4(ra1, &Ah[arow][acol + 4], &Al[arow][acol + 4]);
        split_store4(rb0, &Bh[brow][bcol],     &Bl[brow][bcol]);
        split_store4(rb1, &Bh[brow][bcol + 4], &Bl[brow][bcol + 4]);
        __syncthreads();

        // prefetch next tile (latency hidden under MMAs below)
        if (k0 + 16 < Kd) {
            Ap += 16;
            Bp += (size_t)16 * ldb;
            ra0 = *(const float4*)Ap;
            ra1 = *(const float4*)(Ap + 4);
            rb0 = *(const float4*)Bp;
            rb1 = *(const float4*)(Bp + 4);
        }

#pragma unroll
        for (int ks = 0; ks < 2; ks++) {
            const int kk = ks * 8;
            uint32_t ah[4][4], al[4][4], bh[4][2], bl[4][2];
#pragma unroll
            for (int mi = 0; mi < 4; mi++) {
                const float* ph = &Ah[mwarp + mi * 16 + g][kk + tg];
                const float* pl = &Al[mwarp + mi * 16 + g][kk + tg];
                ah[mi][0] = __float_as_uint(ph[0]);
                ah[mi][1] = __float_as_uint(ph[8 * 20]);
                ah[mi][2] = __float_as_uint(ph[4]);
                ah[mi][3] = __float_as_uint(ph[8 * 20 + 4]);
                al[mi][0] = __float_as_uint(pl[0]);
                al[mi][1] = __float_as_uint(pl[8 * 20]);
                al[mi][2] = __float_as_uint(pl[4]);
                al[mi][3] = __float_as_uint(pl[8 * 20 + 4]);
            }
#pragma unroll
            for (int ni = 0; ni < 4; ni++) {
                const float* ph = &Bh[kk + tg][nwarp + ni * 8 + g];
                const float* pl = &Bl[kk + tg][nwarp + ni * 8 + g];
                bh[ni][0] = __float_as_uint(ph[0]);
                bh[ni][1] = __float_as_uint(ph[4 * 136]);
                bl[ni][0] = __float_as_uint(pl[0]);
                bl[ni][1] = __float_as_uint(pl[4 * 136]);
            }
#pragma unroll
            for (int mi = 0; mi < 4; mi++)
#pragma unroll
                for (int ni = 0; ni < 4; ni++) {
                    mma_tf32(acc[mi][ni], al[mi], bh[ni]);
                    mma_tf32(acc[mi][ni], ah[mi], bl[ni]);
                    mma_tf32(acc[mi][ni], ah[mi], bh[ni]);
                }
        }
        __syncthreads();
    }

#pragma unroll
    for (int mi = 0; mi < 4; mi++) {
#pragma unroll
        for (int ni = 0; ni < 4; ni++) {
            const int r0 = bm * 128 + mwarp + mi * 16 + g;
            const int c  = bn * 128 + nwarp + ni * 8 + 2 * tg;
            const float2 bb = *(const float2*)&bias[c];
            float2 o0 = make_float2(acc[mi][ni][0] + bb.x, acc[mi][ni][1] + bb.y);
            float2 o1 = make_float2(acc[mi][ni][2] + bb.x, acc[mi][ni][3] + bb.y);
            if (res) {
                const float2 r0v = *(const float2*)&res[(size_t)r0 * ldc + c];
                const float2 r1v = *(const float2*)&res[(size_t)(r0 + 8) * ldc + c];
                o0.x += r0v.x; o0.y += r0v.y;
                o1.x += r1v.x; o1.y += r1v.y;
            }
            *(float2*)&C[(size_t)r0 * ldc + c]       = o0;
            *(float2*)&C[(size_t)(r0 + 8) * ldc + c] = o1;
        }
    }
}

// ---------------- MMA flash attention (tf32 tensor cores) ---------------------
// (unchanged from R6 — known correct)
__global__ void __launch_bounds__(128) attn_mma_kernel(const float* __restrict__ q,
                                                       const float* __restrict__ k,
                                                       const float* __restrict__ v,
                                                       const float* __restrict__ mask,
                                                       float* __restrict__ ctx)
{
    const int qt = blockIdx.x, head = blockIdx.y, b = blockIdx.z;
    const int tid  = threadIdx.x;
    const int w    = tid >> 5;
    const int lane = tid & 31;
    const int g    = lane >> 2;
    const int tg   = lane & 3;

    __shared__ float KsPs[64][68];
    __shared__ float Vs[64][72];
    __shared__ float Msk[64];

    const size_t q0 = (size_t)(b * SEQ + qt * 64 + 16 * w) * HD + head * DHEAD;
    uint32_t qa[8][4];
#pragma unroll
    for (int kj = 0; kj < 8; kj++) {
        const int c = 8 * kj + tg;
        qa[kj][0] = tf32b(q[q0 + (size_t)g * HD + c]);
        qa[kj][1] = tf32b(q[q0 + (size_t)(g + 8) * HD + c]);
        qa[kj][2] = tf32b(q[q0 + (size_t)g * HD + c + 4]);
        qa[kj][3] = tf32b(q[q0 + (size_t)(g + 8) * HD + c + 4]);
    }

    float oacc[8][4];
#pragma unroll
    for (int di = 0; di < 8; di++)
#pragma unroll
        for (int c = 0; c < 4; c++) oacc[di][c] = 0.f;
    float m0 = -1e30f, m1 = -1e30f, l0 = 0.f, l1 = 0.f;

    const int r  = tid >> 1;
    const int cb = (tid & 1) * 32;

    for (int kt = 0; kt < SEQ / 64; kt++) {
        __syncthreads();
        {
            const size_t kvrow = (size_t)(b * SEQ + kt * 64 + r) * HD + head * DHEAD + cb;
            const float4* kp = (const float4*)(k + kvrow);
            const float4* vp = (const float4*)(v + kvrow);
#pragma unroll
            for (int i = 0; i < 8; i++) {
                float4 kv4 = kp[i];
                kv4.x = tf32r(kv4.x); kv4.y = tf32r(kv4.y);
                kv4.z = tf32r(kv4.z); kv4.w = tf32r(kv4.w);
                *(float4*)&KsPs[r][cb + 4 * i] = kv4;
                float4 vv4 = vp[i];
                vv4.x = tf32r(vv4.x); vv4.y = tf32r(vv4.y);
                vv4.z = tf32r(vv4.z); vv4.w = tf32r(vv4.w);
                *(float4*)&Vs[r][cb + 4 * i] = vv4;
            }
            if (tid < 64) Msk[tid] = -1000.f * (1.f - mask[b * SEQ + kt * 64 + tid]);
        }
        __syncthreads();

        float sacc[8][4];
#pragma unroll
        for (int ni = 0; ni < 8; ni++) {
            sacc[ni][0] = sacc[ni][1] = sacc[ni][2] = sacc[ni][3] = 0.f;
#pragma unroll
            for (int kj = 0; kj < 8; kj++) {
                uint32_t bb[2];
                bb[0] = __float_as_uint(KsPs[8 * ni + g][8 * kj + tg]);
                bb[1] = __float_as_uint(KsPs[8 * ni + g][8 * kj + tg + 4]);
                mma_tf32(sacc[ni], qa[kj], bb);
            }
        }
#pragma unroll
        for (int ni = 0; ni < 8; ni++) {
            const int c0 = 8 * ni + 2 * tg;
            sacc[ni][0] = sacc[ni][0] * 0.125f + Msk[c0];
            sacc[ni][1] = sacc[ni][1] * 0.125f + Msk[c0 + 1];
            sacc[ni][2] = sacc[ni][2] * 0.125f + Msk[c0];
            sacc[ni][3] = sacc[ni][3] * 0.125f + Msk[c0 + 1];
        }
        float t0 = -1e30f, t1 = -1e30f;
#pragma unroll
        for (int ni = 0; ni < 8; ni++) {
            t0 = fmaxf(t0, fmaxf(sacc[ni][0], sacc[ni][1]));
            t1 = fmaxf(t1, fmaxf(sacc[ni][2], sacc[ni][3]));
        }
        t0 = fmaxf(t0, __shfl_xor_sync(0xffffffffu, t0, 1));
        t0 = fmaxf(t0, __shfl_xor_sync(0xffffffffu, t0, 2));
        t1 = fmaxf(t1, __shfl_xor_sync(0xffffffffu, t1, 1));
        t1 = fmaxf(t1, __shfl_xor_sync(0xffffffffu, t1, 2));
        const float nm0 = fmaxf(m0, t0), nm1 = fmaxf(m1, t1);
        const float cr0 = __expf(m0 - nm0), cr1 = __expf(m1 - nm1);
        m0 = nm0; m1 = nm1;
        float ls0 = 0.f, ls1 = 0.f;
#pragma unroll
        for (int ni = 0; ni < 8; ni++) {
            sacc[ni][0] = __expf(sacc[ni][0] - nm0);
            sacc[ni][1] = __expf(sacc[ni][1] - nm0);
            sacc[ni][2] = __expf(sacc[ni][2] - nm1);
            sacc[ni][3] = __expf(sacc[ni][3] - nm1);
            ls0 += sacc[ni][0] + sacc[ni][1];
            ls1 += sacc[ni][2] + sacc[ni][3];
        }
        ls0 += __shfl_xor_sync(0xffffffffu, ls0, 1);
        ls0 += __shfl_xor_sync(0xffffffffu, ls0, 2);
        ls1 += __shfl_xor_sync(0xffffffffu, ls1, 1);
        ls1 += __shfl_xor_sync(0xffffffffu, ls1, 2);
        l0 = l0 * cr0 + ls0;
        l1 = l1 * cr1 + ls1;
#pragma unroll
        for (int di = 0; di < 8; di++) {
            oacc[di][0] *= cr0; oacc[di][1] *= cr0;
            oacc[di][2] *= cr1; oacc[di][3] *= cr1;
        }
        __syncthreads();
#pragma unroll
        for (int ni = 0; ni < 8; ni++) {
            const int c0 = 8 * ni + 2 * tg;
            float2 p0 = make_float2(tf32r(sacc[ni][0]), tf32r(sacc[ni][1]));
            float2 p1 = make_float2(tf32r(sacc[ni][2]), tf32r(sacc[ni][3]));
            *(float2*)&KsPs[16 * w + g][c0]     = p0;
            *(float2*)&KsPs[16 * w + g + 8][c0] = p1;
        }
        __syncwarp();

#pragma unroll
        for (int kj = 0; kj < 8; kj++) {
            uint32_t pa[4];
            const int c = 8 * kj + tg;
            pa[0] = __float_as_uint(KsPs[16 * w + g][c]);
            pa[1] = __float_as_uint(KsPs[16 * w + g + 8][c]);
            pa[2] = __float_as_uint(KsPs[16 * w + g][c + 4]);
            pa[3] = __float_as_uint(KsPs[16 * w + g + 8][c + 4]);
#pragma unroll
            for (int di = 0; di < 8; di++) {
                uint32_t bb[2];
                bb[0] = __float_as_uint(Vs[8 * kj + tg][8 * di + g]);
                bb[1] = __float_as_uint(Vs[8 * kj + tg + 4][8 * di + g]);
                mma_tf32(oacc[di], pa, bb);
            }
        }
    }

    const float i0 = 1.f / l0, i1 = 1.f / l1;
    const size_t o0 = (size_t)(b * SEQ + qt * 64 + 16 * w) * HD + head * DHEAD;
#pragma unroll
    for (int di = 0; di < 8; di++) {
        const int c = 8 * di + 2 * tg;
        float2 r0v = make_float2(oacc[di][0] * i0, oacc[di][1] * i0);
        float2 r1v = make_float2(oacc[di][2] * i1, oacc[di][3] * i1);
        *(float2*)&ctx[o0 + (size_t)g * HD + c]       = r0v;
        *(float2*)&ctx[o0 + (size_t)(g + 8) * HD + c] = r1v;
    }
}

// ---------------- top-k over 256 sign-pattern logits: 1 warp per (n,t) -------
__global__ void __launch_bounds__(256) topk_kernel(const float* __restrict__ hs,
                                                   float* __restrict__ wout,
                                                   int* __restrict__ iout)
{
    const int warp = (blockIdx.x * blockDim.x + threadIdx.x) >> 5;
    const int lane = threadIdx.x & 31;
    const float* hp = hs + (size_t)warp * 8;
    float h[8];
#pragma unroll
    for (int i = 0; i < 8; i++) h[i] = hp[i];

    float lg[8];
#pragma unroll
    for (int i = 0; i < 8; i++) {
        const int c = lane * 8 + i;
        float acc = 0.f;
#pragma unroll
        for (int bb = 0; bb < 8; bb++)
            acc += ((c >> bb) & 1) ? h[bb] : -h[bb];
        lg[i] = acc;
    }

    float m0 = 0.f, sum = 0.f, myv = 0.f;
    int myc = 0;
#pragma unroll
    for (int it = 0; it < 8; it++) {
        float lv = -1e30f;
        int lc = 0;
#pragma unroll
        for (int i = 0; i < 8; i++)
            if (lg[i] > lv) { lv = lg[i]; lc = lane * 8 + i; }
#pragma unroll
        for (int off = 16; off; off >>= 1) {
            const float ov = __shfl_down_sync(0xffffffffu, lv, off);
            const int   oc = __shfl_down_sync(0xffffffffu, lc, off);
            if (ov > lv || (ov == lv && oc < lc)) { lv = ov; lc = oc; }
        }
        lv = __shfl_sync(0xffffffffu, lv, 0);
        lc = __shfl_sync(0xffffffffu, lc, 0);
        if (it == 0) m0 = lv;
        sum += __expf(lv - m0);
        if (lane == it) { myv = lv; myc = lc; }
        if (lane == (lc >> 3)) {
            const int ii = lc & 7;
#pragma unroll
            for (int i = 0; i < 8; i++)
                if (i == ii) lg[i] = -1e30f;
        }
    }
    if (lane < 8) {
        wout[(size_t)warp * 8 + lane] = __expf(myv - m0) / sum;
        iout[(size_t)warp * 8 + lane] = myc;
    }
}

// ---------------- gather FFN (bf16 tables) + residual: 1 block per token ------
__global__ void __launch_bounds__(256) ffn_kernel(const __nv_bfloat16* __restrict__ tables,
                                                  const float* __restrict__ tbias,
                                                  const float* __restrict__ attn,
                                                  const float* __restrict__ wbuf,
                                                  const int* __restrict__ ibuf,
                                                  float* __restrict__ out)
{
    const int n = blockIdx.x;
    const int tid = threadIdx.x;
    __shared__ float sw[512];
    __shared__ int   si[512];
    sw[tid]       = wbuf[(size_t)n * 512 + tid];
    sw[tid + 256] = wbuf[(size_t)n * 512 + 256 + tid];
    si[tid]       = ibuf[(size_t)n * 512 + tid];
    si[tid + 256] = ibuf[(size_t)n * 512 + 256 + tid];
    __syncthreads();

    float4 acc = make_float4(0.f, 0.f, 0.f, 0.f);
    const int hb = tid * 4;
#pragma unroll 4
    for (int p = 0; p < 512; p++) {
        const int tt = p >> 3;
        const uint2 raw = *(const uint2*)&tables[((size_t)tt * TSZ + si[p]) * HD + hb];
        const float2 r0 = __bfloat1622float2(*(const __nv_bfloat162*)&raw.x);
        const float2 r1 = __bfloat1622float2(*(const __nv_bfloat162*)&raw.y);
        const float wv = sw[p];
        acc.x += wv * r0.x; acc.y += wv * r0.y;
        acc.z += wv * r1.x; acc.w += wv * r1.y;
    }
    const float4 bb = *(const float4*)&tbias[hb];
    const float4 aa = *(const float4*)&attn[(size_t)n * HD + hb];
    float4 o;
    o.x = acc.x + bb.x + aa.x;
    o.y = acc.y + bb.y + aa.y;
    o.z = acc.z + bb.z + aa.z;
    o.w = acc.w + bb.w + aa.w;
    *(float4*)&out[(size_t)n * HD + hb] = o;
}

// ---------------- launcher ----------------------------------------------------
extern "C" void kernel_launch(void* const* d_in, const int* in_sizes, int n_in,
                              void* d_out, int out_size)
{
    const float* hidden = (const float*)d_in[0];
    const float* amask  = (const float*)d_in[1];
    const float* ln1g   = (const float*)d_in[2];
    const float* ln1b   = (const float*)d_in[3];
    const float* Wq     = (const float*)d_in[4];
    const float* bq     = (const float*)d_in[5];
    const float* Wk     = (const float*)d_in[6];
    const float* bk     = (const float*)d_in[7];
    const float* Wv     = (const float*)d_in[8];
    const float* bv     = (const float*)d_in[9];
    const float* Wo     = (const float*)d_in[10];
    const float* bo     = (const float*)d_in[11];
    const float* ln2g   = (const float*)d_in[12];
    const float* ln2b   = (const float*)d_in[13];
    const float* Wh     = (const float*)d_in[14];
    const float* bh     = (const float*)d_in[15];
    const float* tw     = (const float*)d_in[16];
    const float* tb     = (const float*)d_in[17];
    float* out = (float*)d_out;

    float *x, *q, *k, *v, *ctx, *attn, *y, *hsb, *wb;
    __nv_bfloat16* tbl;
    int* ib;
    cudaGetSymbolAddress((void**)&x,    g_x);
    cudaGetSymbolAddress((void**)&q,    g_q);
    cudaGetSymbolAddress((void**)&k,    g_k);
    cudaGetSymbolAddress((void**)&v,    g_v);
    cudaGetSymbolAddress((void**)&ctx,  g_ctx);
    cudaGetSymbolAddress((void**)&attn, g_attn);
    cudaGetSymbolAddress((void**)&y,    g_y);
    cudaGetSymbolAddress((void**)&hsb,  g_hs);
    cudaGetSymbolAddress((void**)&wb,   g_w);
    cudaGetSymbolAddress((void**)&ib,   g_i);
    cudaGetSymbolAddress((void**)&tbl,  g_tbl);

    // 0. convert tables to bf16
    tbl_bf16_kernel<<<(TT * TSZ * HD) / (256 * 8), 256>>>(tw, tbl);

    // 1. LN1
    ln_kernel<<<NTOK, 256>>>(hidden, ln1g, ln1b, x);

    // 2. QKV projections (3xTF32 tensor cores)
    dim3 gqkv(HD / 128, NTOK / 128);
    gemm_tf32_kernel<<<gqkv, 256>>>(x, Wq, bq, nullptr, q, HD, HD, HD);
    gemm_tf32_kernel<<<gqkv, 256>>>(x, Wk, bk, nullptr, k, HD, HD, HD);
    gemm_tf32_kernel<<<gqkv, 256>>>(x, Wv, bv, nullptr, v, HD, HD, HD);

    // 3. attention (tf32 MMA flash)
    attn_mma_kernel<<<dim3(SEQ / 64, NHEADS, NB), 128>>>(q, k, v, amask, ctx);

    // 4. output projection + residual
    gemm_tf32_kernel<<<gqkv, 256>>>(ctx, Wo, bo, hidden, attn, HD, HD, HD);

    // 5. LN2
    ln_kernel<<<NTOK, 256>>>(attn, ln2g, ln2b, y);

    // 6. table-head projection (first 512 cols of Wh)
    gemm_tf32_kernel<<<dim3(512 / 128, NTOK / 128), 256>>>(y, Wh, bh, nullptr, hsb, HD, HD, 512);

    // 7. sign-pattern logits + top-8 + softmax weights
    topk_kernel<<<(NTOK * TT) / 8, 256>>>(hsb, wb, ib);

    // 8. gather FFN (bf16 tables) + bias + attn residual -> out
    ffn_kernel<<<NTOK, 256>>>(tbl, tb, attn, wb, ib, out);
}